// round 14
// baseline (speedup 1.0000x reference)
#include <cuda_runtime.h>
#include <cuda_fp16.h>
#include <cstdint>

// ---------------- problem constants ----------------
#define Bsz   64
#define Tlen  2048
#define HID   512
#define HCLS  1024
#define DOUT  10

#define MT    64                        // rows per CTA
#define NCH   128                       // N per chunk (4 chunks cover 512)
#define KCH   64                        // K per cp.async chunk
#define NCTA  ((Bsz * Tlen) / MT)       // 2048
#define CPB   (Tlen / MT)               // 32 chunks per batch

// ---------------- device scratch ----------------
__device__ __align__(16) __half g_Wt_hi[HID][HID];   // W^T fp16 [n][k]
__device__ __align__(16) __half g_W1h[HID * HCLS];   // W1 fp16 [k][j]
__device__ float g_pctx[NCTA * HID];
__device__ float g_m[NCTA];
__device__ float g_s[NCTA];
__device__ float g_hidden[Bsz * HCLS];
__device__ int   g_cnt[Bsz];

// ---------------- SMEM layout (dynamic, scores kernel) ----------------
#define SM_A     0                       // 64 KB (64 x 512 fp16, swizzled)
#define SM_B     65536                   // 2 buffers x 16384 = 32 KB
#define SM_BIAS  98304
#define SM_CW    100352
#define SM_RS    102400
#define SM_PW    102656
#define SM_RED   102912
#define SM_TOTAL 103168

// ---------------- helpers ----------------
__device__ __forceinline__ float fast_tanh(float x) {
    x = fminf(fmaxf(x, -15.f), 15.f);
    float e = __expf(2.f * x);
    return __fdividef(e - 1.f, e + 1.f);
}

__device__ __forceinline__ uint32_t smem_u32(const void* p) {
    uint32_t a;
    asm("{ .reg .u64 t; cvta.to.shared.u64 t, %1; cvt.u32.u64 %0, t; }" : "=r"(a) : "l"(p));
    return a;
}

__device__ __forceinline__ void ldsm_x4(uint32_t* r, uint32_t addr) {
    asm volatile("ldmatrix.sync.aligned.m8n8.x4.shared.b16 {%0,%1,%2,%3}, [%4];"
                 : "=r"(r[0]), "=r"(r[1]), "=r"(r[2]), "=r"(r[3]) : "r"(addr));
}
__device__ __forceinline__ void ldsm_x2(uint32_t* r, uint32_t addr) {
    asm volatile("ldmatrix.sync.aligned.m8n8.x2.shared.b16 {%0,%1}, [%2];"
                 : "=r"(r[0]), "=r"(r[1]) : "r"(addr));
}
__device__ __forceinline__ void mma_f16(float* d, const uint32_t* a, const uint32_t* b) {
    asm volatile("mma.sync.aligned.m16n8k16.row.col.f32.f16.f16.f32 "
                 "{%0,%1,%2,%3}, {%4,%5,%6,%7}, {%8,%9}, {%0,%1,%2,%3};"
                 : "+f"(d[0]), "+f"(d[1]), "+f"(d[2]), "+f"(d[3])
                 : "r"(a[0]), "r"(a[1]), "r"(a[2]), "r"(a[3]), "r"(b[0]), "r"(b[1]));
}
__device__ __forceinline__ void cp16(uint32_t dst, const void* gsrc) {
    uint64_t g = __cvta_generic_to_global((void*)gsrc);
    asm volatile("cp.async.ca.shared.global [%0], [%1], 16;" :: "r"(dst), "l"(g) : "memory");
}
#define CP_COMMIT() asm volatile("cp.async.commit_group;" ::: "memory")
#define CP_WAIT0()  asm volatile("cp.async.wait_group 0;" ::: "memory")

// ---------------------------------------------------------------------------
// Prep: W -> W^T fp16 (tile transpose); W1 -> fp16; zero g_hidden + g_cnt.
// grid = 64 blocks x 256 threads.
// ---------------------------------------------------------------------------
__global__ __launch_bounds__(256) void prep_kernel(const float* __restrict__ W,
                                                   const float* __restrict__ W1)
{
    __shared__ __half tile[64][65];
    const int bk = (blockIdx.x >> 3) * 64;
    const int bn = (blockIdx.x & 7) * 64;
    const int t = threadIdx.x;

    {
        int r  = t >> 2;
        int c0 = (t & 3) * 16;
        const float4* src = (const float4*)&W[(size_t)(bk + r) * HID + bn + c0];
        #pragma unroll
        for (int q = 0; q < 4; ++q) {
            float4 v = src[q];
            tile[r][c0 + q*4 + 0] = __float2half_rn(v.x);
            tile[r][c0 + q*4 + 1] = __float2half_rn(v.y);
            tile[r][c0 + q*4 + 2] = __float2half_rn(v.z);
            tile[r][c0 + q*4 + 3] = __float2half_rn(v.w);
        }
    }
    __syncthreads();
    {
        int n  = t >> 2;
        int k0 = (t & 3) * 16;
        union { __half h[16]; uint4 q[2]; } o;
        #pragma unroll
        for (int i = 0; i < 16; ++i) o.h[i] = tile[k0 + i][n];
        uint4* dst = (uint4*)&g_Wt_hi[bn + n][bk + k0];
        dst[0] = o.q[0];
        dst[1] = o.q[1];
    }
    const int gt = blockIdx.x * 256 + t;       // 0..16383
    for (int i = gt; i < Bsz * HCLS; i += 64 * 256)
        g_hidden[i] = 0.f;
    if (gt < Bsz) g_cnt[gt] = 0;
    // W1 fp32 -> fp16 (coalesced float4 read, half2x2 = 8B write)
    for (int i = gt; i < (HID * HCLS) / 4; i += 64 * 256) {
        float4 v = __ldg((const float4*)&W1[(size_t)i * 4]);
        __half2* d = (__half2*)&g_W1h[(size_t)i * 4];
        d[0] = __floats2half2_rn(v.x, v.y);
        d[1] = __floats2half2_rn(v.z, v.w);
    }
}

// ---------------------------------------------------------------------------
// Scores + local softmax + partial ctx (from SMEM fp16 A). 64 rows/CTA;
// 2 CTAs/SM; single-pass fp16 mma.sync; ONE barrier per k-chunk.
// ---------------------------------------------------------------------------
__global__ __launch_bounds__(256, 2) void scores_kernel(
    const float* __restrict__ emb,
    const float* __restrict__ bias,
    const float* __restrict__ cw)
{
    extern __shared__ char smem[];
    const uint32_t sb = smem_u32(smem);
    const int t    = threadIdx.x;
    const int wid  = t >> 5;
    const int lane = t & 31;
    const int warpM = wid >> 2;      // 0..1
    const int warpN = wid & 3;       // 0..3
    const int row0 = blockIdx.x * MT;

    float* sbias = (float*)(smem + SM_BIAS);
    float* scw   = (float*)(smem + SM_CW);
    float* rs    = (float*)(smem + SM_RS);
    float* pw    = (float*)(smem + SM_PW);
    float* red   = (float*)(smem + SM_RED);

    for (int i = t; i < HID; i += 256) { sbias[i] = bias[i]; scw[i] = cw[i]; }
    if (t < MT) rs[t] = 0.f;

    // ---- A: load 64x512 fp32, convert fp16, store swizzled (once) ----
    for (int task = t; task < MT * 64; task += 256) {
        int row = task >> 6;
        int c   = task & 63;                     // 16B chunk (8 fp16)
        const float4* src = (const float4*)&emb[(size_t)(row0 + row) * HID + c * 8];
        float4 v0 = src[0], v1 = src[1];
        float x[8] = {v0.x, v0.y, v0.z, v0.w, v1.x, v1.y, v1.z, v1.w};
        union { __half h[8]; uint4 q; } uh;
        #pragma unroll
        for (int q = 0; q < 8; ++q) uh.h[q] = __float2half_rn(x[q]);
        uint32_t off = (uint32_t)(row * 1024 + ((c ^ (row & 7)) << 4));
        *(uint4*)(smem + SM_A + off) = uh.q;
    }
    __syncthreads();

    // lane -> ldmatrix address components
    const int g4 = lane >> 3;
    const int aRowOff = ((g4 & 1) << 3) + (lane & 7);
    const int aCadd   = g4 >> 1;
    const int bRowOff = lane & 7;
    const int bCadd   = (lane >> 3) & 1;

    for (int nc = 0; nc < 4; ++nc) {
        const int n0 = nc * NCH;
        float acc[2][4][4] = {};

        // prologue: issue k-chunk 0 into buf0
        {
            for (int task = t; task < 1024; task += 256) {
                int n = task >> 3, c = task & 7;
                const char* src = (const char*)&g_Wt_hi[0][0] +
                    ((size_t)(n0 + n) * HID + c * 8) * 2;
                uint32_t dst = sb + SM_B + n * 128 + ((c ^ (n & 7)) << 4);
                cp16(dst, src);
            }
            CP_COMMIT();
        }

        for (int kc = 0; kc < 8; ++kc) {
            CP_WAIT0();
            __syncthreads();
            if (kc < 7) {
                int kn = kc + 1;
                uint32_t bufn = SM_B + (kn & 1) * 16384;
                for (int task = t; task < 1024; task += 256) {
                    int n = task >> 3, c = task & 7;
                    const char* src = (const char*)&g_Wt_hi[0][0] +
                        ((size_t)(n0 + n) * HID + kn * KCH + c * 8) * 2;
                    uint32_t dst = sb + bufn + n * 128 + ((c ^ (n & 7)) << 4);
                    cp16(dst, src);
                }
                CP_COMMIT();
            }

            const uint32_t bb = sb + SM_B + (kc & 1) * 16384;
            #pragma unroll
            for (int ks = 0; ks < 4; ++ks) {
                const int ckA = kc * 8 + ks * 2;
                uint32_t Ah[2][4], Bh[4][2];
                #pragma unroll
                for (int mt = 0; mt < 2; ++mt) {
                    int row = warpM * 32 + mt * 16 + aRowOff;
                    uint32_t ca = (uint32_t)((ckA + aCadd) ^ (row & 7));
                    ldsm_x4(Ah[mt], sb + SM_A + row * 1024 + (ca << 4));
                }
                #pragma unroll
                for (int nt = 0; nt < 4; ++nt) {
                    int nrow = warpN * 32 + nt * 8 + bRowOff;
                    uint32_t cb = (uint32_t)((ks * 2 + bCadd) ^ (nrow & 7));
                    ldsm_x2(Bh[nt], bb + nrow * 128 + (cb << 4));
                }
                #pragma unroll
                for (int mt = 0; mt < 2; ++mt)
                    #pragma unroll
                    for (int nt = 0; nt < 4; ++nt)
                        mma_f16(acc[mt][nt], Ah[mt], Bh[nt]);
            }
        }

        // ---- tanh(acc+bias)*cw, reduce this N-chunk into rs ----
        #pragma unroll
        for (int mt = 0; mt < 2; ++mt) {
            float s0 = 0.f, s1 = 0.f;
            #pragma unroll
            for (int nt = 0; nt < 4; ++nt) {
                int c0 = n0 + warpN * 32 + nt * 8 + (lane & 3) * 2;
                float b0 = sbias[c0], b1 = sbias[c0 + 1];
                float w0 = scw[c0],   w1 = scw[c0 + 1];
                s0 += fast_tanh(acc[mt][nt][0] + b0) * w0
                    + fast_tanh(acc[mt][nt][1] + b1) * w1;
                s1 += fast_tanh(acc[mt][nt][2] + b0) * w0
                    + fast_tanh(acc[mt][nt][3] + b1) * w1;
            }
            s0 += __shfl_xor_sync(0xffffffffu, s0, 1);
            s0 += __shfl_xor_sync(0xffffffffu, s0, 2);
            s1 += __shfl_xor_sync(0xffffffffu, s1, 1);
            s1 += __shfl_xor_sync(0xffffffffu, s1, 2);
            if ((lane & 3) == 0) {
                int r = warpM * 32 + mt * 16 + (lane >> 2);
                atomicAdd(&rs[r], s0);
                atomicAdd(&rs[r + 8], s1);
            }
        }
    }
    __syncthreads();

    // ---- local softmax over this chunk's 64 scores ----
    if (t < MT) red[t] = fast_tanh(rs[t]);
    __syncthreads();
    if (t < MT) rs[t] = red[t];
    if (t < MT) {
        float v = rs[t];
        #pragma unroll
        for (int o = 16; o > 0; o >>= 1) v = fmaxf(v, __shfl_xor_sync(0xffffffffu, v, o));
        if (lane == 0) red[wid] = v;
    }
    __syncthreads();
    const float mloc = fmaxf(red[0], red[1]);
    if (t < MT) pw[t] = __expf(rs[t] - mloc);
    __syncthreads();
    if (t < MT) {
        float v = pw[t];
        #pragma unroll
        for (int o = 16; o > 0; o >>= 1) v += __shfl_xor_sync(0xffffffffu, v, o);
        if (lane == 0) red[8 + wid] = v;
    }
    __syncthreads();
    if (t == 0) {
        g_m[blockIdx.x] = mloc;
        g_s[blockIdx.x] = red[8] + red[9];
    }

    // ---- partial ctx from SMEM fp16 A: pctx[h] = sum_t pw[t]*A[t][h] ----
    {
        const int h2 = t * 2;
        const int c  = h2 >> 3;
        const int w8 = (h2 & 7) * 2;
        float a0 = 0.f, a1 = 0.f;
        #pragma unroll 8
        for (int tt = 0; tt < MT; ++tt) {
            uint32_t off = (uint32_t)(tt * 1024 + ((c ^ (tt & 7)) << 4) + w8);
            uint32_t v = *(const uint32_t*)(smem + SM_A + off);
            __half2 hv = *reinterpret_cast<const __half2*>(&v);
            float w = pw[tt];
            a0 += w * __half2float(__low2half(hv));
            a1 += w * __half2float(__high2half(hv));
        }
        *(float2*)&g_pctx[(size_t)blockIdx.x * HID + h2] = make_float2(a0, a1);
    }
}

// ---------------------------------------------------------------------------
// Hidden (fused combine, fp16 W1) + last-block logits+softmax.
// grid (Bsz, HKS) = (64, 8), 256 threads.
// ---------------------------------------------------------------------------
#define HKS 8
#define HKC (HID / HKS)   // 64

__global__ __launch_bounds__(256) void hidden_kernel(
    const float* __restrict__ b1,
    const float* __restrict__ W2, const float* __restrict__ b2,
    float* __restrict__ out)
{
    const int b  = blockIdx.x;
    const int k0 = blockIdx.y * HKC;
    const int t  = threadIdx.x;
    const int wid = t >> 5;
    const int lane = t & 31;
    __shared__ float wexp[CPB];
    __shared__ float sinv;
    __shared__ float sc[HKC];
    __shared__ float part[8][DOUT];
    __shared__ int   slast;

    // combine weights (recomputed per block; 32 exps)
    if (t < CPB) {
        float m = g_m[b * CPB + t];
        float M = m;
        #pragma unroll
        for (int o = 16; o > 0; o >>= 1)
            M = fmaxf(M, __shfl_xor_sync(0xffffffffu, M, o));
        float w = __expf(m - M);
        wexp[t] = w;
        float d = w * g_s[b * CPB + t];
        #pragma unroll
        for (int o = 16; o > 0; o >>= 1)
            d += __shfl_xor_sync(0xffffffffu, d, o);
        if (t == 0) sinv = __frcp_rn(d);
    }
    __syncthreads();

    if (t < HKC) {
        float acc = 0.f;
        #pragma unroll 4
        for (int c = 0; c < CPB; ++c)
            acc += wexp[c] * g_pctx[((size_t)(b * CPB + c)) * HID + k0 + t];
        sc[t] = acc * sinv;
    }
    __syncthreads();

    // hidden slice: j0 = t*4, fp16 W1 loads (2 x half2 per k)
    const int j0 = t * 4;
    float4 a;
    if (blockIdx.y == 0) a = *(const float4*)&b1[j0];
    else                 a = make_float4(0.f, 0.f, 0.f, 0.f);

    #pragma unroll 8
    for (int h = 0; h < HKC; ++h) {
        const __half2* wp = (const __half2*)&g_W1h[(size_t)(k0 + h) * HCLS + j0];
        float2 w01 = __half22float2(wp[0]);
        float2 w23 = __half22float2(wp[1]);
        float s = sc[h];
        a.x += s * w01.x; a.y += s * w01.y; a.z += s * w23.x; a.w += s * w23.y;
    }
    atomicAdd(&g_hidden[b * HCLS + j0 + 0], a.x);
    atomicAdd(&g_hidden[b * HCLS + j0 + 1], a.y);
    atomicAdd(&g_hidden[b * HCLS + j0 + 2], a.z);
    atomicAdd(&g_hidden[b * HCLS + j0 + 3], a.w);

    // last-block-does-logits
    __threadfence();
    __syncthreads();
    if (t == 0) {
        int done = atomicAdd(&g_cnt[b], 1);
        slast = (done == HKS - 1);
    }
    __syncthreads();
    if (!slast) return;
    __threadfence();

    // logits: 256 threads x 4 hidden units each
    float p[DOUT];
    #pragma unroll
    for (int o = 0; o < DOUT; ++o) p[o] = 0.f;
    #pragma unroll
    for (int q = 0; q < 4; ++q) {
        int h = t * 4 + q;
        float hv = fmaxf(g_hidden[b * HCLS + h], 0.f);
        #pragma unroll
        for (int o = 0; o < DOUT; ++o)
            p[o] += hv * __ldg(&W2[(size_t)h * DOUT + o]);
    }
    #pragma unroll
    for (int o = 0; o < DOUT; ++o) {
        #pragma unroll
        for (int s = 16; s > 0; s >>= 1)
            p[o] += __shfl_xor_sync(0xffffffffu, p[o], s);
    }
    if (lane == 0) {
        #pragma unroll
        for (int o = 0; o < DOUT; ++o) part[wid][o] = p[o];
    }
    __syncthreads();
    if (t == 0) {
        float logits[DOUT];
        float mx = -1e30f;
        #pragma unroll
        for (int o = 0; o < DOUT; ++o) {
            float q = 0.f;
            #pragma unroll
            for (int w = 0; w < 8; ++w) q += part[w][o];
            logits[o] = q + __ldg(&b2[o]);
            mx = fmaxf(mx, logits[o]);
        }
        float s = 0.f, ex[DOUT];
        #pragma unroll
        for (int o = 0; o < DOUT; ++o) { ex[o] = __expf(logits[o] - mx); s += ex[o]; }
        const float inv = 1.f / s;
        #pragma unroll
        for (int o = 0; o < DOUT; ++o) out[b * DOUT + o] = ex[o] * inv;
    }
}

// ---------------------------------------------------------------------------
// Launch. Inputs: numerical, embedding, weight, bias, context_weight,
// W1, b1, W2, b2. Output: [B, DOUT] float32.
// ---------------------------------------------------------------------------
extern "C" void kernel_launch(void* const* d_in, const int* in_sizes, int n_in,
                              void* d_out, int out_size)
{
    (void)in_sizes; (void)n_in; (void)out_size;
    const float* emb  = (const float*)d_in[1];
    const float* W    = (const float*)d_in[2];
    const float* bias = (const float*)d_in[3];
    const float* cw   = (const float*)d_in[4];
    const float* W1   = (const float*)d_in[5];
    const float* b1   = (const float*)d_in[6];
    const float* W2   = (const float*)d_in[7];
    const float* b2   = (const float*)d_in[8];
    float* out = (float*)d_out;

    static bool attr_set = false;
    if (!attr_set) {
        cudaFuncSetAttribute(scores_kernel,
                             cudaFuncAttributeMaxDynamicSharedMemorySize, SM_TOTAL);
        attr_set = true;
    }

    prep_kernel<<<64, 256>>>(W, W1);
    scores_kernel<<<NCTA, 256, SM_TOTAL>>>(emb, bias, cw);
    hidden_kernel<<<dim3(Bsz, HKS), 256>>>(b1, W2, b2, out);
}

// round 15
// speedup vs baseline: 1.0412x; 1.0412x over previous
#include <cuda_runtime.h>
#include <cuda_fp16.h>
#include <cstdint>

// ---------------- problem constants ----------------
#define Bsz   64
#define Tlen  2048
#define HID   512
#define HCLS  1024
#define DOUT  10

#define MT    64                        // rows per CTA
#define NCH   128                       // N per chunk (4 chunks cover 512)
#define KCH   64                        // K per cp.async chunk
#define NCTA  ((Bsz * Tlen) / MT)       // 2048
#define CPB   (Tlen / MT)               // 32 chunks per batch

// ---------------- device scratch ----------------
__device__ __align__(16) __half g_Wt_hi[HID][HID];   // W^T fp16 [n][k]
__device__ float g_pctx[NCTA * HID];
__device__ float g_m[NCTA];
__device__ float g_s[NCTA];
__device__ float g_hidden[Bsz * HCLS];

// ---------------- SMEM layout (dynamic) ----------------
#define SM_A     0                       // 64 KB (64 x 512 fp16, swizzled)
#define SM_B     65536                   // 2 buffers x 16384 = 32 KB
#define SM_BIAS  98304
#define SM_CW    100352
#define SM_RS    102400
#define SM_PW    102656
#define SM_RED   102912
#define SM_TOTAL 103168

// ---------------- helpers ----------------
__device__ __forceinline__ float fast_tanh(float x) {
    x = fminf(fmaxf(x, -15.f), 15.f);
    float e = __expf(2.f * x);
    return __fdividef(e - 1.f, e + 1.f);
}

__device__ __forceinline__ uint32_t smem_u32(const void* p) {
    uint32_t a;
    asm("{ .reg .u64 t; cvta.to.shared.u64 t, %1; cvt.u32.u64 %0, t; }" : "=r"(a) : "l"(p));
    return a;
}

__device__ __forceinline__ void ldsm_x4(uint32_t* r, uint32_t addr) {
    asm volatile("ldmatrix.sync.aligned.m8n8.x4.shared.b16 {%0,%1,%2,%3}, [%4];"
                 : "=r"(r[0]), "=r"(r[1]), "=r"(r[2]), "=r"(r[3]) : "r"(addr));
}
__device__ __forceinline__ void mma_f16(float* d, const uint32_t* a, const uint32_t* b) {
    asm volatile("mma.sync.aligned.m16n8k16.row.col.f32.f16.f16.f32 "
                 "{%0,%1,%2,%3}, {%4,%5,%6,%7}, {%8,%9}, {%0,%1,%2,%3};"
                 : "+f"(d[0]), "+f"(d[1]), "+f"(d[2]), "+f"(d[3])
                 : "r"(a[0]), "r"(a[1]), "r"(a[2]), "r"(a[3]), "r"(b[0]), "r"(b[1]));
}
__device__ __forceinline__ void cp16(uint32_t dst, const void* gsrc) {
    uint64_t g = __cvta_generic_to_global((void*)gsrc);
    asm volatile("cp.async.ca.shared.global [%0], [%1], 16;" :: "r"(dst), "l"(g) : "memory");
}
#define CP_COMMIT() asm volatile("cp.async.commit_group;" ::: "memory")
#define CP_WAIT0()  asm volatile("cp.async.wait_group 0;" ::: "memory")

// ---------------------------------------------------------------------------
// Prep: W[k][n] fp32 -> W^T[n][k] fp16 via SMEM tile transpose. Also zeroes
// g_hidden. grid = 64 blocks x 256 threads.
// ---------------------------------------------------------------------------
__global__ __launch_bounds__(256) void prep_kernel(const float* __restrict__ W)
{
    __shared__ __half tile[64][65];
    const int bk = (blockIdx.x >> 3) * 64;
    const int bn = (blockIdx.x & 7) * 64;
    const int t = threadIdx.x;

    {
        int r  = t >> 2;
        int c0 = (t & 3) * 16;
        const float4* src = (const float4*)&W[(size_t)(bk + r) * HID + bn + c0];
        #pragma unroll
        for (int q = 0; q < 4; ++q) {
            float4 v = src[q];
            tile[r][c0 + q*4 + 0] = __float2half_rn(v.x);
            tile[r][c0 + q*4 + 1] = __float2half_rn(v.y);
            tile[r][c0 + q*4 + 2] = __float2half_rn(v.z);
            tile[r][c0 + q*4 + 3] = __float2half_rn(v.w);
        }
    }
    __syncthreads();
    {
        int n  = t >> 2;
        int k0 = (t & 3) * 16;
        union { __half h[16]; uint4 q[2]; } o;
        #pragma unroll
        for (int i = 0; i < 16; ++i) o.h[i] = tile[k0 + i][n];
        uint4* dst = (uint4*)&g_Wt_hi[bn + n][bk + k0];
        dst[0] = o.q[0];
        dst[1] = o.q[1];
    }
    for (int i = blockIdx.x * 256 + t; i < Bsz * HCLS; i += 64 * 256)
        g_hidden[i] = 0.f;
}

// ---------------------------------------------------------------------------
// Scores + local softmax + partial ctx (from SMEM fp16 A). 64 rows/CTA;
// 2 CTAs/SM; single-pass fp16 mma.sync; ONE barrier per k-chunk;
// B loaded with paired ldmatrix.x4 (2 instrs for 4 operand pairs).
// ---------------------------------------------------------------------------
__global__ __launch_bounds__(256, 2) void scores_kernel(
    const float* __restrict__ emb,
    const float* __restrict__ bias,
    const float* __restrict__ cw)
{
    extern __shared__ char smem[];
    const uint32_t sb = smem_u32(smem);
    const int t    = threadIdx.x;
    const int wid  = t >> 5;
    const int lane = t & 31;
    const int warpM = wid >> 2;      // 0..1
    const int warpN = wid & 3;       // 0..3
    const int row0 = blockIdx.x * MT;

    float* sbias = (float*)(smem + SM_BIAS);
    float* scw   = (float*)(smem + SM_CW);
    float* rs    = (float*)(smem + SM_RS);
    float* pw    = (float*)(smem + SM_PW);
    float* red   = (float*)(smem + SM_RED);

    for (int i = t; i < HID; i += 256) { sbias[i] = bias[i]; scw[i] = cw[i]; }
    if (t < MT) rs[t] = 0.f;

    // ---- A: load 64x512 fp32, convert fp16, store swizzled (once) ----
    for (int task = t; task < MT * 64; task += 256) {
        int row = task >> 6;
        int c   = task & 63;                     // 16B chunk (8 fp16)
        const float4* src = (const float4*)&emb[(size_t)(row0 + row) * HID + c * 8];
        float4 v0 = src[0], v1 = src[1];
        float x[8] = {v0.x, v0.y, v0.z, v0.w, v1.x, v1.y, v1.z, v1.w};
        union { __half h[8]; uint4 q; } uh;
        #pragma unroll
        for (int q = 0; q < 8; ++q) uh.h[q] = __float2half_rn(x[q]);
        uint32_t off = (uint32_t)(row * 1024 + ((c ^ (row & 7)) << 4));
        *(uint4*)(smem + SM_A + off) = uh.q;
    }
    __syncthreads();

    // lane -> ldmatrix address components
    const int g4 = lane >> 3;
    const int aRowOff = ((g4 & 1) << 3) + (lane & 7);
    const int aCadd   = g4 >> 1;
    const int bRowOff = lane & 7;
    const int bCadd   = (lane >> 3) & 1;         // k-half select
    const int bNSel   = (lane >> 4) & 1;         // nt-pair select (x4 B load)

    for (int nc = 0; nc < 4; ++nc) {
        const int n0 = nc * NCH;
        float acc[2][4][4] = {};

        // prologue: issue k-chunk 0 into buf0
        {
            for (int task = t; task < 1024; task += 256) {
                int n = task >> 3, c = task & 7;
                const char* src = (const char*)&g_Wt_hi[0][0] +
                    ((size_t)(n0 + n) * HID + c * 8) * 2;
                uint32_t dst = sb + SM_B + n * 128 + ((c ^ (n & 7)) << 4);
                cp16(dst, src);
            }
            CP_COMMIT();
        }

        for (int kc = 0; kc < 8; ++kc) {
            CP_WAIT0();
            __syncthreads();
            if (kc < 7) {
                int kn = kc + 1;
                uint32_t bufn = SM_B + (kn & 1) * 16384;
                for (int task = t; task < 1024; task += 256) {
                    int n = task >> 3, c = task & 7;
                    const char* src = (const char*)&g_Wt_hi[0][0] +
                        ((size_t)(n0 + n) * HID + kn * KCH + c * 8) * 2;
                    uint32_t dst = sb + bufn + n * 128 + ((c ^ (n & 7)) << 4);
                    cp16(dst, src);
                }
                CP_COMMIT();
            }

            const uint32_t bb = sb + SM_B + (kc & 1) * 16384;
            #pragma unroll
            for (int ks = 0; ks < 4; ++ks) {
                const int ckA = kc * 8 + ks * 2;
                uint32_t Ah[2][4], Bq[2][4];
                #pragma unroll
                for (int mt = 0; mt < 2; ++mt) {
                    int row = warpM * 32 + mt * 16 + aRowOff;
                    uint32_t ca = (uint32_t)((ckA + aCadd) ^ (row & 7));
                    ldsm_x4(Ah[mt], sb + SM_A + row * 1024 + (ca << 4));
                }
                // B: one x4 covers nt pair {2np, 2np+1}:
                // lanes 0-7:(nt,k0) 8-15:(nt,k1) 16-23:(nt+1,k0) 24-31:(nt+1,k1)
                #pragma unroll
                for (int np = 0; np < 2; ++np) {
                    int nrow = warpN * 32 + (np * 2 + bNSel) * 8 + bRowOff;
                    uint32_t cb = (uint32_t)((ks * 2 + bCadd) ^ (nrow & 7));
                    ldsm_x4(Bq[np], bb + nrow * 128 + (cb << 4));
                }
                #pragma unroll
                for (int mt = 0; mt < 2; ++mt)
                    #pragma unroll
                    for (int np = 0; np < 2; ++np) {
                        mma_f16(acc[mt][np * 2 + 0], Ah[mt], &Bq[np][0]);
                        mma_f16(acc[mt][np * 2 + 1], Ah[mt], &Bq[np][2]);
                    }
            }
        }

        // ---- tanh(acc+bias)*cw, reduce this N-chunk into rs ----
        #pragma unroll
        for (int mt = 0; mt < 2; ++mt) {
            float s0 = 0.f, s1 = 0.f;
            #pragma unroll
            for (int nt = 0; nt < 4; ++nt) {
                int c0 = n0 + warpN * 32 + nt * 8 + (lane & 3) * 2;
                float b0 = sbias[c0], b1 = sbias[c0 + 1];
                float w0 = scw[c0],   w1 = scw[c0 + 1];
                s0 += fast_tanh(acc[mt][nt][0] + b0) * w0
                    + fast_tanh(acc[mt][nt][1] + b1) * w1;
                s1 += fast_tanh(acc[mt][nt][2] + b0) * w0
                    + fast_tanh(acc[mt][nt][3] + b1) * w1;
            }
            s0 += __shfl_xor_sync(0xffffffffu, s0, 1);
            s0 += __shfl_xor_sync(0xffffffffu, s0, 2);
            s1 += __shfl_xor_sync(0xffffffffu, s1, 1);
            s1 += __shfl_xor_sync(0xffffffffu, s1, 2);
            if ((lane & 3) == 0) {
                int r = warpM * 32 + mt * 16 + (lane >> 2);
                atomicAdd(&rs[r], s0);
                atomicAdd(&rs[r + 8], s1);
            }
        }
    }
    __syncthreads();

    // ---- local softmax over this chunk's 64 scores ----
    if (t < MT) red[t] = fast_tanh(rs[t]);
    __syncthreads();
    if (t < MT) rs[t] = red[t];
    if (t < MT) {
        float v = rs[t];
        #pragma unroll
        for (int o = 16; o > 0; o >>= 1) v = fmaxf(v, __shfl_xor_sync(0xffffffffu, v, o));
        if (lane == 0) red[wid] = v;
    }
    __syncthreads();
    const float mloc = fmaxf(red[0], red[1]);
    if (t < MT) pw[t] = __expf(rs[t] - mloc);
    __syncthreads();
    if (t < MT) {
        float v = pw[t];
        #pragma unroll
        for (int o = 16; o > 0; o >>= 1) v += __shfl_xor_sync(0xffffffffu, v, o);
        if (lane == 0) red[8 + wid] = v;
    }
    __syncthreads();
    if (t == 0) {
        g_m[blockIdx.x] = mloc;
        g_s[blockIdx.x] = red[8] + red[9];
    }

    // ---- partial ctx from SMEM fp16 A: pctx[h] = sum_t pw[t]*A[t][h] ----
    {
        const int h2 = t * 2;
        const int c  = h2 >> 3;
        const int w8 = (h2 & 7) * 2;
        float a0 = 0.f, a1 = 0.f;
        #pragma unroll 8
        for (int tt = 0; tt < MT; ++tt) {
            uint32_t off = (uint32_t)(tt * 1024 + ((c ^ (tt & 7)) << 4) + w8);
            uint32_t v = *(const uint32_t*)(smem + SM_A + off);
            __half2 hv = *reinterpret_cast<const __half2*>(&v);
            float w = pw[tt];
            a0 += w * __half2float(__low2half(hv));
            a1 += w * __half2float(__high2half(hv));
        }
        *(float2*)&g_pctx[(size_t)blockIdx.x * HID + h2] = make_float2(a0, a1);
    }
}

// ---------------------------------------------------------------------------
// Hidden layer with fused combine. grid (Bsz, HKS) = (64, 8), 256 threads.
// ---------------------------------------------------------------------------
#define HKS 8
#define HKC (HID / HKS)   // 64

__global__ __launch_bounds__(256) void hidden_kernel(
    const float* __restrict__ W1, const float* __restrict__ b1)
{
    const int b  = blockIdx.x;
    const int k0 = blockIdx.y * HKC;
    const int t  = threadIdx.x;
    __shared__ float wexp[CPB];
    __shared__ float sinv;
    __shared__ float sc[HKC];

    if (t < CPB) {
        float m = g_m[b * CPB + t];
        float M = m;
        #pragma unroll
        for (int o = 16; o > 0; o >>= 1)
            M = fmaxf(M, __shfl_xor_sync(0xffffffffu, M, o));
        float w = __expf(m - M);
        wexp[t] = w;
        float d = w * g_s[b * CPB + t];
        #pragma unroll
        for (int o = 16; o > 0; o >>= 1)
            d += __shfl_xor_sync(0xffffffffu, d, o);
        if (t == 0) sinv = __frcp_rn(d);
    }
    __syncthreads();

    if (t < HKC) {
        float acc = 0.f;
        #pragma unroll 4
        for (int c = 0; c < CPB; ++c)
            acc += wexp[c] * g_pctx[((size_t)(b * CPB + c)) * HID + k0 + t];
        sc[t] = acc * sinv;
    }
    __syncthreads();

    const int j0 = t * 4;
    float4 a;
    if (blockIdx.y == 0) a = *(const float4*)&b1[j0];
    else                 a = make_float4(0.f, 0.f, 0.f, 0.f);

    #pragma unroll 8
    for (int h = 0; h < HKC; ++h) {
        float4 w = __ldg((const float4*)&W1[(size_t)(k0 + h) * HCLS + j0]);
        float s = sc[h];
        a.x += s * w.x; a.y += s * w.y; a.z += s * w.z; a.w += s * w.w;
    }
    atomicAdd(&g_hidden[b * HCLS + j0 + 0], a.x);
    atomicAdd(&g_hidden[b * HCLS + j0 + 1], a.y);
    atomicAdd(&g_hidden[b * HCLS + j0 + 2], a.z);
    atomicAdd(&g_hidden[b * HCLS + j0 + 3], a.w);
}

// ---------------------------------------------------------------------------
// Logits + softmax. grid = B, 1024 threads.
// ---------------------------------------------------------------------------
__global__ __launch_bounds__(1024) void logits_kernel(
    const float* __restrict__ W2, const float* __restrict__ b2,
    float* __restrict__ out)
{
    const int b = blockIdx.x;
    const int t = threadIdx.x;
    const int wid = t >> 5;
    const int lane = t & 31;
    __shared__ float part[32][DOUT];

    const float hv = fmaxf(g_hidden[b * HCLS + t], 0.f);
    float p[DOUT];
    #pragma unroll
    for (int o = 0; o < DOUT; ++o) p[o] = hv * __ldg(&W2[(size_t)t * DOUT + o]);

    #pragma unroll
    for (int o = 0; o < DOUT; ++o) {
        #pragma unroll
        for (int s = 16; s > 0; s >>= 1) p[o] += __shfl_xor_sync(0xffffffffu, p[o], s);
    }
    if (lane == 0) {
        #pragma unroll
        for (int o = 0; o < DOUT; ++o) part[wid][o] = p[o];
    }
    __syncthreads();

    if (t < 32) {
        float q[DOUT];
        #pragma unroll
        for (int o = 0; o < DOUT; ++o) q[o] = part[t][o];
        #pragma unroll
        for (int o = 0; o < DOUT; ++o) {
            #pragma unroll
            for (int s = 16; s > 0; s >>= 1) q[o] += __shfl_xor_sync(0xffffffffu, q[o], s);
        }
        if (t == 0) {
            float logits[DOUT];
            float mx = -1e30f;
            #pragma unroll
            for (int o = 0; o < DOUT; ++o) {
                logits[o] = q[o] + __ldg(&b2[o]);
                mx = fmaxf(mx, logits[o]);
            }
            float s = 0.f, ex[DOUT];
            #pragma unroll
            for (int o = 0; o < DOUT; ++o) { ex[o] = __expf(logits[o] - mx); s += ex[o]; }
            const float inv = 1.f / s;
            #pragma unroll
            for (int o = 0; o < DOUT; ++o) out[b * DOUT + o] = ex[o] * inv;
        }
    }
}

// ---------------------------------------------------------------------------
// Launch. Inputs: numerical, embedding, weight, bias, context_weight,
// W1, b1, W2, b2. Output: [B, DOUT] float32.
// ---------------------------------------------------------------------------
extern "C" void kernel_launch(void* const* d_in, const int* in_sizes, int n_in,
                              void* d_out, int out_size)
{
    (void)in_sizes; (void)n_in; (void)out_size;
    const float* emb  = (const float*)d_in[1];
    const float* W    = (const float*)d_in[2];
    const float* bias = (const float*)d_in[3];
    const float* cw   = (const float*)d_in[4];
    const float* W1   = (const float*)d_in[5];
    const float* b1   = (const float*)d_in[6];
    const float* W2   = (const float*)d_in[7];
    const float* b2   = (const float*)d_in[8];
    float* out = (float*)d_out;

    static bool attr_set = false;
    if (!attr_set) {
        cudaFuncSetAttribute(scores_kernel,
                             cudaFuncAttributeMaxDynamicSharedMemorySize, SM_TOTAL);
        attr_set = true;
    }

    prep_kernel<<<64, 256>>>(W);
    scores_kernel<<<NCTA, 256, SM_TOTAL>>>(emb, bias, cw);
    hidden_kernel<<<dim3(Bsz, HKS), 256>>>(W1, b1);
    logits_kernel<<<Bsz, 1024>>>(W2, b2, out);
}